// round 10
// baseline (speedup 1.0000x reference)
#include <cuda_runtime.h>
#include <math.h>

#define SPH 132            // Fcs/H1s row stride (floats)
#define H2P 130            // H2s row stride (floats)

// dynamic smem layout (floats)
#define OFF_W1B 0          // [128 m][64 k]           8192
#define OFF_W2  8192       // [128 m][128 k]         16384
#define OFF_FCS 24576      // [64 k][SPH]             8448
#define OFF_H1  33024      // [128 m][SPH] (alias H2) 16896
#define OFF_US  49920      // [8 row][128 m]          1024
#define SMEM_FLOATS 50944  // 203776 bytes

// ---------------- device scratch -------------------------------------------
__device__ float  g_U[(size_t)50000 * 128];  // exact 64-term prefix chains
__device__ float  g_z[800000];               // fp32 z (bitwise target)
__device__ double g_part[1024];              // per-CTA sum of z^2 (fp64)
__device__ float  g_norm32;                  // fl32(max(sqrt(sum), 1e-12))

// ---------------- f32x2 helpers (two independent fp32 FMAs, bitwise = fmaf) -
static __device__ __forceinline__ unsigned long long ffma2(
    unsigned long long a, unsigned long long b, unsigned long long c) {
    unsigned long long d;
    asm("fma.rn.f32x2 %0, %1, %2, %3;" : "=l"(d) : "l"(a), "l"(b), "l"(c));
    return d;
}
static __device__ __forceinline__ unsigned long long dup2(float a) {
    unsigned long long d; unsigned int ai = __float_as_uint(a);
    asm("mov.b64 %0, {%1, %1};" : "=l"(d) : "r"(ai));
    return d;
}
static __device__ __forceinline__ void unpack2(unsigned long long v, float& lo, float& hi) {
    unsigned int l, h;
    asm("mov.b64 {%0, %1}, %2;" : "=r"(l), "=r"(h) : "l"(v));
    lo = __uint_as_float(l); hi = __uint_as_float(h);
}

// ---------------- stage 1: U[n][m] = serial FMA chain over k=0..63 ----------
__global__ __launch_bounds__(256)
void node_u_kernel(const float* __restrict__ feats,
                   const float* __restrict__ W1, int N)
{
    __shared__ float fs[64 * 64];
    const int tid = threadIdx.x;
    const int h = tid & 127;
    const int half = tid >> 7;
    const int n0 = blockIdx.x * 64;
    int cnt = N - n0; if (cnt > 64) cnt = 64;
    if (cnt <= 0) return;

    float w[64];
    const float4* wp = (const float4*)(W1 + h * 128);
#pragma unroll
    for (int i = 0; i < 16; i++) {
        float4 q = __ldg(wp + i);
        w[4*i] = q.x; w[4*i+1] = q.y; w[4*i+2] = q.z; w[4*i+3] = q.w;
    }
    const float4* fsrc = (const float4*)(feats + (size_t)n0 * 64);
    for (int i = tid; i < cnt * 16; i += 256)
        ((float4*)fs)[i] = __ldg(fsrc + i);
    __syncthreads();

    const int nb = half * 32;
    const int ne = (cnt < nb + 32) ? cnt : (nb + 32);
    for (int nn = nb; nn < ne; nn++) {
        const float* fp = fs + nn * 64;
        float acc = 0.f;
#pragma unroll
        for (int k = 0; k < 64; k++) acc = fmaf(w[k], fp[k], acc);  // serial ascending
        g_U[(size_t)(n0 + nn) * 128 + h] = acc;
    }
}

// ---------------- gather helper (strided over `nt` threads) -----------------
static __device__ __forceinline__ void gather_tile(
    float* Fcs, float* Us, const int* rows, const int* cols,
    const float* feats, int e0, int E, int t, int nt)
{
    for (int idx = t; idx < 2048; idx += nt) {
        int e = idx >> 4, kq = idx & 15;
        int g = e0 + e;
        float4 q = make_float4(0.f, 0.f, 0.f, 0.f);
        if (g < E) {
            int c = __ldg(cols + g);
            q = __ldg((const float4*)(feats + (size_t)c * 64) + kq);
        }
        Fcs[(kq*4+0)*SPH + e] = q.x;
        Fcs[(kq*4+1)*SPH + e] = q.y;
        Fcs[(kq*4+2)*SPH + e] = q.z;
        Fcs[(kq*4+3)*SPH + e] = q.w;
    }
    for (int i = t; i < 1024; i += nt) {
        int r = i >> 7, m = i & 127;
        int ge = e0 + r * 16;
        int grow = (ge < E) ? __ldg(rows + ge) : 0;
        Us[i] = g_U[(size_t)grow * 128 + m];
    }
}

// ---------------- stage 2: persistent edge kernel, layers 1-3 ---------------
// 512 threads: tx = tid&31 (4 contiguous edges), ty = tid>>5 (8 m rows)
__global__ __launch_bounds__(512, 1)
void edge_kernel(const int* __restrict__ rows, const int* __restrict__ cols,
                 const float* __restrict__ feats,
                 const float* __restrict__ W1g, const float* __restrict__ b1g,
                 const float* __restrict__ W2g, const float* __restrict__ b2g,
                 const float* __restrict__ W3g, const float* __restrict__ b3g,
                 int E, int EB)
{
    extern __shared__ float smem[];
    float* W1bs = smem + OFF_W1B;
    float* W2s  = smem + OFF_W2;
    float* Fcs  = smem + OFF_FCS;
    float* H1s  = smem + OFF_H1;
    float* H2s  = H1s;                  // phase C alias: [128 e][H2P]
    float* Us   = smem + OFF_US;

    __shared__ float  W3s[128];
    __shared__ double dred[4];

    const int tid = threadIdx.x;

    // ---- resident weights (loaded once) ----
    {
        const float4* w1v = (const float4*)W1g;
#pragma unroll
        for (int it = 0; it < 4; it++) {
            int idx = tid + it * 512;
            int m = idx >> 4, kq = idx & 15;
            ((float4*)W1bs)[idx] = __ldg(w1v + m * 32 + 16 + kq);  // W1[m][64+4kq..]
        }
        const float4* src = (const float4*)W2g;
        float4* dst = (float4*)W2s;
#pragma unroll 4
        for (int it = 0; it < 8; it++)
            dst[tid + it*512] = __ldg(src + tid + it*512);
        if (tid < 128) W3s[tid] = __ldg(W3g + tid);
    }

    const int tx = tid & 31;            // edges tx*4 .. tx*4+3 (2 f32x2 pairs)
    const int ty = tid >> 5;            // m = ty*8 + i, i in [0,8)
    const float b3v = __ldg(b3g);
    double sq_acc = 0.0;

    int tile = blockIdx.x;
    if (tile < EB)
        gather_tile(Fcs, Us, rows, cols, feats, tile * 128, E, tid, 512);
    __syncthreads();

    for (; tile < EB; tile += gridDim.x) {
        const int e0 = tile * 128;
        unsigned long long acc[8][2];

        // ---- phase A: continue layer-1 chain over col half (k=64..127) ----
        {
            const int r = tx >> 2;      // all 4 edges share one row
#pragma unroll
            for (int i = 0; i < 8; i++) {
                unsigned long long u = dup2(Us[r*128 + ty*8 + i]);
                acc[i][0] = u; acc[i][1] = u;
            }
            const float* ap = W1bs + (ty*8) * 64;
#pragma unroll 2
            for (int k4 = 0; k4 < 16; k4++) {
                float a[8][4];
#pragma unroll
                for (int i = 0; i < 8; i++) {
                    float4 q = *(const float4*)(ap + i*64 + k4*4);
                    a[i][0]=q.x; a[i][1]=q.y; a[i][2]=q.z; a[i][3]=q.w;
                }
#pragma unroll
                for (int kk = 0; kk < 4; kk++) {
                    const float* bk = Fcs + (k4*4 + kk) * SPH;
                    ulonglong2 q0 = *(const ulonglong2*)(bk + tx*4);
#pragma unroll
                    for (int i = 0; i < 8; i++) {
                        unsigned long long ad = dup2(a[i][kk]);
                        acc[i][0] = ffma2(ad, q0.x, acc[i][0]);
                        acc[i][1] = ffma2(ad, q0.y, acc[i][1]);
                    }
                }
            }
#pragma unroll
            for (int i = 0; i < 8; i++) {
                int m = ty*8 + i;
                float bb = __ldg(b1g + m);
#pragma unroll
                for (int p = 0; p < 2; p++) {
                    float lo, hi; unpack2(acc[i][p], lo, hi);
                    int e = tx*4 + p*2;
                    H1s[m*SPH + e]     = fmaxf(lo + bb, 0.f);
                    H1s[m*SPH + e + 1] = fmaxf(hi + bb, 0.f);
                }
            }
        }
        __syncthreads();

        // ---- phase B: layer-2 serial ascending-k chain ----
#pragma unroll
        for (int i = 0; i < 8; i++) { acc[i][0] = 0ULL; acc[i][1] = 0ULL; }
        {
            const float* ap = W2s + (ty*8) * 128;
#pragma unroll 2
            for (int k4 = 0; k4 < 32; k4++) {
                float a[8][4];
#pragma unroll
                for (int i = 0; i < 8; i++) {
                    float4 q = *(const float4*)(ap + i*128 + k4*4);
                    a[i][0]=q.x; a[i][1]=q.y; a[i][2]=q.z; a[i][3]=q.w;
                }
#pragma unroll
                for (int kk = 0; kk < 4; kk++) {
                    const float* bk = H1s + (k4*4 + kk) * SPH;
                    ulonglong2 q0 = *(const ulonglong2*)(bk + tx*4);
#pragma unroll
                    for (int i = 0; i < 8; i++) {
                        unsigned long long ad = dup2(a[i][kk]);
                        acc[i][0] = ffma2(ad, q0.x, acc[i][0]);
                        acc[i][1] = ffma2(ad, q0.y, acc[i][1]);
                    }
                }
            }
        }
        __syncthreads();   // all H1s reads done before aliasing it as H2s
#pragma unroll
        for (int i = 0; i < 8; i++) {
            int m = ty*8 + i;
            float bb = __ldg(b2g + m);
#pragma unroll
            for (int p = 0; p < 2; p++) {
                float lo, hi; unpack2(acc[i][p], lo, hi);
                int e = tx*4 + p*2;
                H2s[e*H2P + m]     = fmaxf(lo + bb, 0.f);
                H2s[(e+1)*H2P + m] = fmaxf(hi + bb, 0.f);
            }
        }
        __syncthreads();

        // ---- phase C (tid<128): z chain; tid>=128: prefetch next tile ----
        if (tid < 128) {
            const float* hrow = H2s + tid * H2P;
            float z = 0.f;
#pragma unroll
            for (int m = 0; m < 128; m++)
                z = fmaf(W3s[m], hrow[m], z);      // serial, ascending (GEMM order)
            z = z + b3v;                           // b3 = 0: exact

            int g = e0 + tid;
            if (g < E) {
                g_z[g] = z;
                sq_acc += (double)z * (double)z;
            }
        } else {
            int nt = tile + gridDim.x;
            if (nt < EB)
                gather_tile(Fcs, Us, rows, cols, feats, nt * 128, E, tid - 128, 384);
        }
        __syncthreads();
    }

    // ---- per-CTA deterministic sum of z^2 ----
    if (tid < 128) {
        double s = sq_acc;
#pragma unroll
        for (int m2 = 16; m2; m2 >>= 1)
            s += __shfl_xor_sync(0xffffffffu, s, m2);
        if ((tid & 31) == 0) dred[tid >> 5] = s;
    }
    __syncthreads();
    if (tid == 0)
        g_part[blockIdx.x] = (dred[0] + dred[1]) + (dred[2] + dred[3]);
}

// ---------------- stage 3: exact (fp64) ||z||, rounded to fp32 --------------
__global__ void reduce_partials_kernel(int nb)
{
    __shared__ double sm[256];
    double s = 0.0;
    for (int i = threadIdx.x; i < nb; i += 256) s += g_part[i];
    sm[threadIdx.x] = s;
    __syncthreads();
    for (int st = 128; st > 0; st >>= 1) {
        if (threadIdx.x < st) sm[threadIdx.x] += sm[threadIdx.x + st];
        __syncthreads();
    }
    if (threadIdx.x == 0)
        g_norm32 = (float)fmax(sqrt(sm[0]), 1e-12);
}

// ---------------- stage 4: fp32-faithful softmax + top-8 with fp32 ties -----
__global__ __launch_bounds__(256)
void finalize_kernel(float* __restrict__ out, int N)
{
    const int t = blockIdx.x * 256 + threadIdx.x;
    const int warp = t >> 5;
    const int lane = threadIdx.x & 31;
    const int row = warp * 2 + (lane >> 4);
    const int j = lane & 15;
    const bool valid = row < N;
    const int e = row * 16 + j;

    const float nrm = g_norm32;
    float zn = valid ? __fdiv_rn(g_z[e], nrm) : -1e30f;   // fp32 division, as ref

    float mx = zn;
#pragma unroll
    for (int m = 8; m; m >>= 1)
        mx = fmaxf(mx, __shfl_xor_sync(0xffffffffu, mx, m, 16));

    const float a = zn - mx;                              // fp32 subtract, as ref
    float ez = (float)exp((double)a);                     // ~correctly-rounded expf
    if (!valid) ez = 0.f;

    // segment_sum emulation: fp32 adds in ascending index order
    float s = 0.f;
#pragma unroll
    for (int i = 0; i < 16; i++)
        s += __shfl_sync(0xffffffffu, ez, i, 16);

    const float pi = __fdiv_rn(ez, s);                    // fp32 division, as ref

    // keep iff at most 7 strictly-greater pi in the row (ties at 8th kept)
    int r = 0;
#pragma unroll
    for (int i = 0; i < 16; i++) {
        float v = __shfl_sync(0xffffffffu, pi, i, 16);
        r += (v > pi) ? 1 : 0;
    }
    if (valid) out[e] = (r <= 7) ? pi : 0.f;
}

// ---------------- launch ----------------------------------------------------
extern "C" void kernel_launch(void* const* d_in, const int* in_sizes, int n_in,
                              void* d_out, int out_size)
{
    const float* feats = (const float*)d_in[0];
    const int*   idx   = (const int*)  d_in[1];
    const float* W1    = (const float*)d_in[2];
    const float* b1    = (const float*)d_in[3];
    const float* W2    = (const float*)d_in[4];
    const float* b2    = (const float*)d_in[5];
    const float* W3    = (const float*)d_in[6];
    const float* b3    = (const float*)d_in[7];
    float* out = (float*)d_out;

    const int N = in_sizes[0] / 64;
    const int E = in_sizes[1] / 2;
    const int* rows = idx;
    const int* cols = idx + E;

    static int nsm = 0;
    if (nsm == 0) {
        cudaDeviceGetAttribute(&nsm, cudaDevAttrMultiProcessorCount, 0);
        if (nsm <= 0 || nsm > 1024) nsm = 148;
        cudaFuncSetAttribute(edge_kernel,
                             cudaFuncAttributeMaxDynamicSharedMemorySize,
                             SMEM_FLOATS * (int)sizeof(float));
    }

    node_u_kernel<<<(N + 63) / 64, 256>>>(feats, W1, N);

    const int EB = (E + 127) / 128;
    edge_kernel<<<nsm, 512, SMEM_FLOATS * sizeof(float)>>>(
        rows, cols, feats, W1, b1, W2, b2, W3, b3, E, EB);

    reduce_partials_kernel<<<1, 256>>>(nsm);

    finalize_kernel<<<(N + 15) / 16, 256>>>(out, N);
}

// round 11
// speedup vs baseline: 1.0973x; 1.0973x over previous
#include <cuda_runtime.h>
#include <math.h>

#define SPH 132            // Fcs/H1s row stride (floats)
#define H2P 130            // H2s row stride (floats)

// dynamic smem layout (floats) — padded for unconditional prefetch
#define OFF_W1B 0          // [128 m][64 k] + 16 pad          8208
#define OFF_W2  8208       // [128 m][128 k] + 16 pad        16400
#define OFF_FCS 24608      // [65 k][SPH] (row 64 = pad)      8580
#define OFF_H1  33188      // [129 m][SPH] (row 128 = pad)   17028
#define OFF_US  50216      // [8 row][128 m]                  1024
#define SMEM_FLOATS 51240  // 204960 bytes

// ---------------- device scratch -------------------------------------------
__device__ float  g_U[(size_t)50000 * 128];  // exact 64-term prefix chains
__device__ float  g_z[800000];               // fp32 z (bitwise target)
__device__ double g_part[1024];              // per-CTA sum of z^2 (fp64)
__device__ float  g_norm32;                  // fl32(max(sqrt(sum), 1e-12))

// ---------------- f32x2 helpers (two independent fp32 FMAs, bitwise = fmaf) -
static __device__ __forceinline__ unsigned long long ffma2(
    unsigned long long a, unsigned long long b, unsigned long long c) {
    unsigned long long d;
    asm("fma.rn.f32x2 %0, %1, %2, %3;" : "=l"(d) : "l"(a), "l"(b), "l"(c));
    return d;
}
static __device__ __forceinline__ unsigned long long dup2(float a) {
    unsigned long long d; unsigned int ai = __float_as_uint(a);
    asm("mov.b64 %0, {%1, %1};" : "=l"(d) : "r"(ai));
    return d;
}
static __device__ __forceinline__ void unpack2(unsigned long long v, float& lo, float& hi) {
    unsigned int l, h;
    asm("mov.b64 {%0, %1}, %2;" : "=r"(l), "=r"(h) : "l"(v));
    lo = __uint_as_float(l); hi = __uint_as_float(h);
}

// ---------------- stage 1: U[n][m] = serial FMA chain over k=0..63 ----------
__global__ __launch_bounds__(256)
void node_u_kernel(const float* __restrict__ feats,
                   const float* __restrict__ W1, int N)
{
    __shared__ float fs[64 * 64];
    const int tid = threadIdx.x;
    const int h = tid & 127;
    const int half = tid >> 7;
    const int n0 = blockIdx.x * 64;
    int cnt = N - n0; if (cnt > 64) cnt = 64;
    if (cnt <= 0) return;

    float w[64];
    const float4* wp = (const float4*)(W1 + h * 128);
#pragma unroll
    for (int i = 0; i < 16; i++) {
        float4 q = __ldg(wp + i);
        w[4*i] = q.x; w[4*i+1] = q.y; w[4*i+2] = q.z; w[4*i+3] = q.w;
    }
    const float4* fsrc = (const float4*)(feats + (size_t)n0 * 64);
    for (int i = tid; i < cnt * 16; i += 256)
        ((float4*)fs)[i] = __ldg(fsrc + i);
    __syncthreads();

    const int nb = half * 32;
    const int ne = (cnt < nb + 32) ? cnt : (nb + 32);
    for (int nn = nb; nn < ne; nn++) {
        const float* fp = fs + nn * 64;
        float acc = 0.f;
#pragma unroll
        for (int k = 0; k < 64; k++) acc = fmaf(w[k], fp[k], acc);  // serial ascending
        g_U[(size_t)(n0 + nn) * 128 + h] = acc;
    }
}

// ---------------- gather helper (strided over `nt` threads) -----------------
static __device__ __forceinline__ void gather_tile(
    float* Fcs, float* Us, const int* rows, const int* cols,
    const float* feats, int e0, int E, int t, int nt)
{
    for (int idx = t; idx < 2048; idx += nt) {
        int e = idx >> 4, kq = idx & 15;
        int g = e0 + e;
        float4 q = make_float4(0.f, 0.f, 0.f, 0.f);
        if (g < E) {
            int c = __ldg(cols + g);
            q = __ldg((const float4*)(feats + (size_t)c * 64) + kq);
        }
        Fcs[(kq*4+0)*SPH + e] = q.x;
        Fcs[(kq*4+1)*SPH + e] = q.y;
        Fcs[(kq*4+2)*SPH + e] = q.z;
        Fcs[(kq*4+3)*SPH + e] = q.w;
    }
    for (int i = t; i < 1024; i += nt) {
        int r = i >> 7, m = i & 127;
        int ge = e0 + r * 16;
        int grow = (ge < E) ? __ldg(rows + ge) : 0;
        Us[i] = g_U[(size_t)grow * 128 + m];
    }
}

// ---------------- stage 2: persistent edge kernel, layers 1-3 ---------------
// 256 threads: tx = tid&15 (8 edges: tx*4.. and 64+tx*4..), ty = tid>>4 (8 m)
__global__ __launch_bounds__(256, 1)
void edge_kernel(const int* __restrict__ rows, const int* __restrict__ cols,
                 const float* __restrict__ feats,
                 const float* __restrict__ W1g, const float* __restrict__ b1g,
                 const float* __restrict__ W2g, const float* __restrict__ b2g,
                 const float* __restrict__ W3g, const float* __restrict__ b3g,
                 int E, int EB)
{
    extern __shared__ float smem[];
    float* W1bs = smem + OFF_W1B;
    float* W2s  = smem + OFF_W2;
    float* Fcs  = smem + OFF_FCS;
    float* H1s  = smem + OFF_H1;
    float* H2s  = H1s;                  // phase C alias: [128 e][H2P]
    float* Us   = smem + OFF_US;

    __shared__ float  W3s[128];
    __shared__ double dred[4];

    const int tid = threadIdx.x;

    // ---- resident weights (loaded once) ----
    {
        const float4* w1v = (const float4*)W1g;
#pragma unroll
        for (int it = 0; it < 8; it++) {
            int idx = tid + it * 256;
            int m = idx >> 4, kq = idx & 15;
            *((float4*)(W1bs + m * 64 + kq * 4)) = __ldg(w1v + m * 32 + 16 + kq);
        }
        const float4* src = (const float4*)W2g;
#pragma unroll 4
        for (int it = 0; it < 16; it++) {
            int idx = tid + it * 256;
            *((float4*)(W2s + idx * 4)) = __ldg(src + idx);
        }
        if (tid < 128) W3s[tid] = __ldg(W3g + tid);
    }

    const int tx = tid & 15, ty = tid >> 4;
    const float b3v = __ldg(b3g);
    float bb1[8], bb2[8];
#pragma unroll
    for (int i = 0; i < 8; i++) {
        int m = (i < 4) ? (ty*4 + i) : (64 + ty*4 + (i-4));
        bb1[i] = __ldg(b1g + m);
        bb2[i] = __ldg(b2g + m);
    }
    double sq_acc = 0.0;

    int tile = blockIdx.x;
    if (tile < EB)
        gather_tile(Fcs, Us, rows, cols, feats, tile * 128, E, tid, 256);
    __syncthreads();

    for (; tile < EB; tile += gridDim.x) {
        const int e0 = tile * 128;
        unsigned long long acc[8][4];

        // ================= phase A: layer-1 chain over k=64..127 ===========
        {
            const int rA = tx >> 2, rB = 4 + (tx >> 2);
#pragma unroll
            for (int i = 0; i < 8; i++) {
                int m = (i < 4) ? (ty*4 + i) : (64 + ty*4 + (i-4));
                unsigned long long uA = dup2(Us[rA*128 + m]);
                unsigned long long uB = dup2(Us[rB*128 + m]);
                acc[i][0] = uA; acc[i][1] = uA;
                acc[i][2] = uB; acc[i][3] = uB;
            }
            const float* a0p = W1bs + (ty*4) * 64;
            const float* a1p = W1bs + (64 + ty*4) * 64;

            float ab[2][8][4];
#pragma unroll
            for (int i = 0; i < 4; i++) {                 // prologue a (k4=0)
                float4 q  = *(const float4*)(a0p + i*64);
                ab[0][i][0]=q.x; ab[0][i][1]=q.y; ab[0][i][2]=q.z; ab[0][i][3]=q.w;
                float4 q2 = *(const float4*)(a1p + i*64);
                ab[0][4+i][0]=q2.x; ab[0][4+i][1]=q2.y; ab[0][4+i][2]=q2.z; ab[0][4+i][3]=q2.w;
            }
            ulonglong2 q0 = *(const ulonglong2*)(Fcs + tx*4);        // prologue b (k=0)
            ulonglong2 q1 = *(const ulonglong2*)(Fcs + 64 + tx*4);

#pragma unroll 2
            for (int k4 = 0; k4 < 16; k4++) {
                const int cur = k4 & 1, nxt = cur ^ 1;
#pragma unroll
                for (int i = 0; i < 4; i++) {             // prefetch a (k4+1, padded)
                    float4 q  = *(const float4*)(a0p + i*64 + (k4+1)*4);
                    ab[nxt][i][0]=q.x; ab[nxt][i][1]=q.y; ab[nxt][i][2]=q.z; ab[nxt][i][3]=q.w;
                    float4 q2 = *(const float4*)(a1p + i*64 + (k4+1)*4);
                    ab[nxt][4+i][0]=q2.x; ab[nxt][4+i][1]=q2.y; ab[nxt][4+i][2]=q2.z; ab[nxt][4+i][3]=q2.w;
                }
#pragma unroll
                for (int kk = 0; kk < 4; kk++) {
                    const float* bn = Fcs + (k4*4 + kk + 1) * SPH;   // prefetch b (padded)
                    ulonglong2 n0 = *(const ulonglong2*)(bn + tx*4);
                    ulonglong2 n1 = *(const ulonglong2*)(bn + 64 + tx*4);
#pragma unroll
                    for (int i = 0; i < 8; i++) {
                        unsigned long long ad = dup2(ab[cur][i][kk]);
                        acc[i][0] = ffma2(ad, q0.x, acc[i][0]);
                        acc[i][1] = ffma2(ad, q0.y, acc[i][1]);
                        acc[i][2] = ffma2(ad, q1.x, acc[i][2]);
                        acc[i][3] = ffma2(ad, q1.y, acc[i][3]);
                    }
                    q0 = n0; q1 = n1;
                }
            }
#pragma unroll
            for (int i = 0; i < 8; i++) {
                int m = (i < 4) ? (ty*4 + i) : (64 + ty*4 + (i-4));
                float bb = bb1[i];
#pragma unroll
                for (int p = 0; p < 4; p++) {
                    float lo, hi; unpack2(acc[i][p], lo, hi);
                    int e = (p < 2) ? (tx*4 + p*2) : (64 + tx*4 + (p-2)*2);
                    H1s[m*SPH + e]     = fmaxf(lo + bb, 0.f);
                    H1s[m*SPH + e + 1] = fmaxf(hi + bb, 0.f);
                }
            }
        }
        __syncthreads();

        // ================= phase B: layer-2 serial ascending-k chain ========
#pragma unroll
        for (int i = 0; i < 8; i++)
#pragma unroll
            for (int p = 0; p < 4; p++) acc[i][p] = 0ULL;
        {
            const float* a0p = W2s + (ty*4) * 128;
            const float* a1p = W2s + (64 + ty*4) * 128;

            float ab[2][8][4];
#pragma unroll
            for (int i = 0; i < 4; i++) {                 // prologue a (k4=0)
                float4 q  = *(const float4*)(a0p + i*128);
                ab[0][i][0]=q.x; ab[0][i][1]=q.y; ab[0][i][2]=q.z; ab[0][i][3]=q.w;
                float4 q2 = *(const float4*)(a1p + i*128);
                ab[0][4+i][0]=q2.x; ab[0][4+i][1]=q2.y; ab[0][4+i][2]=q2.z; ab[0][4+i][3]=q2.w;
            }
            ulonglong2 q0 = *(const ulonglong2*)(H1s + tx*4);        // prologue b (k=0)
            ulonglong2 q1 = *(const ulonglong2*)(H1s + 64 + tx*4);

#pragma unroll 2
            for (int k4 = 0; k4 < 32; k4++) {
                const int cur = k4 & 1, nxt = cur ^ 1;
#pragma unroll
                for (int i = 0; i < 4; i++) {             // prefetch a (k4+1, padded)
                    float4 q  = *(const float4*)(a0p + i*128 + (k4+1)*4);
                    ab[nxt][i][0]=q.x; ab[nxt][i][1]=q.y; ab[nxt][i][2]=q.z; ab[nxt][i][3]=q.w;
                    float4 q2 = *(const float4*)(a1p + i*128 + (k4+1)*4);
                    ab[nxt][4+i][0]=q2.x; ab[nxt][4+i][1]=q2.y; ab[nxt][4+i][2]=q2.z; ab[nxt][4+i][3]=q2.w;
                }
#pragma unroll
                for (int kk = 0; kk < 4; kk++) {
                    const float* bn = H1s + (k4*4 + kk + 1) * SPH;   // prefetch b (padded)
                    ulonglong2 n0 = *(const ulonglong2*)(bn + tx*4);
                    ulonglong2 n1 = *(const ulonglong2*)(bn + 64 + tx*4);
#pragma unroll
                    for (int i = 0; i < 8; i++) {
                        unsigned long long ad = dup2(ab[cur][i][kk]);
                        acc[i][0] = ffma2(ad, q0.x, acc[i][0]);
                        acc[i][1] = ffma2(ad, q0.y, acc[i][1]);
                        acc[i][2] = ffma2(ad, q1.x, acc[i][2]);
                        acc[i][3] = ffma2(ad, q1.y, acc[i][3]);
                    }
                    q0 = n0; q1 = n1;
                }
            }
        }
        __syncthreads();   // all H1s reads done before aliasing it as H2s
#pragma unroll
        for (int i = 0; i < 8; i++) {
            int m = (i < 4) ? (ty*4 + i) : (64 + ty*4 + (i-4));
            float bb = bb2[i];
#pragma unroll
            for (int p = 0; p < 4; p++) {
                float lo, hi; unpack2(acc[i][p], lo, hi);
                int e = (p < 2) ? (tx*4 + p*2) : (64 + tx*4 + (p-2)*2);
                H2s[e*H2P + m]     = fmaxf(lo + bb, 0.f);
                H2s[(e+1)*H2P + m] = fmaxf(hi + bb, 0.f);
            }
        }
        __syncthreads();

        // ---- phase C (tid<128): z chain; tid>=128: prefetch next tile ----
        if (tid < 128) {
            const float* hrow = H2s + tid * H2P;
            float z = 0.f;
#pragma unroll
            for (int m = 0; m < 128; m++)
                z = fmaf(W3s[m], hrow[m], z);      // serial, ascending (GEMM order)
            z = z + b3v;                           // b3 = 0: exact

            int g = e0 + tid;
            if (g < E) {
                g_z[g] = z;
                sq_acc += (double)z * (double)z;
            }
        } else {
            int nt = tile + gridDim.x;
            if (nt < EB)
                gather_tile(Fcs, Us, rows, cols, feats, nt * 128, E, tid - 128, 128);
        }
        __syncthreads();
    }

    // ---- per-CTA deterministic sum of z^2 ----
    if (tid < 128) {
        double s = sq_acc;
#pragma unroll
        for (int m2 = 16; m2; m2 >>= 1)
            s += __shfl_xor_sync(0xffffffffu, s, m2);
        if ((tid & 31) == 0) dred[tid >> 5] = s;
    }
    __syncthreads();
    if (tid == 0)
        g_part[blockIdx.x] = (dred[0] + dred[1]) + (dred[2] + dred[3]);
}

// ---------------- stage 3: exact (fp64) ||z||, rounded to fp32 --------------
__global__ void reduce_partials_kernel(int nb)
{
    __shared__ double sm[256];
    double s = 0.0;
    for (int i = threadIdx.x; i < nb; i += 256) s += g_part[i];
    sm[threadIdx.x] = s;
    __syncthreads();
    for (int st = 128; st > 0; st >>= 1) {
        if (threadIdx.x < st) sm[threadIdx.x] += sm[threadIdx.x + st];
        __syncthreads();
    }
    if (threadIdx.x == 0)
        g_norm32 = (float)fmax(sqrt(sm[0]), 1e-12);
}

// ---------------- stage 4: fp32-faithful softmax + top-8 with fp32 ties -----
__global__ __launch_bounds__(256)
void finalize_kernel(float* __restrict__ out, int N)
{
    const int t = blockIdx.x * 256 + threadIdx.x;
    const int warp = t >> 5;
    const int lane = threadIdx.x & 31;
    const int row = warp * 2 + (lane >> 4);
    const int j = lane & 15;
    const bool valid = row < N;
    const int e = row * 16 + j;

    const float nrm = g_norm32;
    float zn = valid ? __fdiv_rn(g_z[e], nrm) : -1e30f;   // fp32 division, as ref

    float mx = zn;
#pragma unroll
    for (int m = 8; m; m >>= 1)
        mx = fmaxf(mx, __shfl_xor_sync(0xffffffffu, mx, m, 16));

    const float a = zn - mx;                              // fp32 subtract, as ref
    float ez = (float)exp((double)a);                     // ~correctly-rounded expf
    if (!valid) ez = 0.f;

    // segment_sum emulation: fp32 adds in ascending index order
    float s = 0.f;
#pragma unroll
    for (int i = 0; i < 16; i++)
        s += __shfl_sync(0xffffffffu, ez, i, 16);

    const float pi = __fdiv_rn(ez, s);                    // fp32 division, as ref

    // keep iff at most 7 strictly-greater pi in the row (ties at 8th kept)
    int r = 0;
#pragma unroll
    for (int i = 0; i < 16; i++) {
        float v = __shfl_sync(0xffffffffu, pi, i, 16);
        r += (v > pi) ? 1 : 0;
    }
    if (valid) out[e] = (r <= 7) ? pi : 0.f;
}

// ---------------- launch ----------------------------------------------------
extern "C" void kernel_launch(void* const* d_in, const int* in_sizes, int n_in,
                              void* d_out, int out_size)
{
    const float* feats = (const float*)d_in[0];
    const int*   idx   = (const int*)  d_in[1];
    const float* W1    = (const float*)d_in[2];
    const float* b1    = (const float*)d_in[3];
    const float* W2    = (const float*)d_in[4];
    const float* b2    = (const float*)d_in[5];
    const float* W3    = (const float*)d_in[6];
    const float* b3    = (const float*)d_in[7];
    float* out = (float*)d_out;

    const int N = in_sizes[0] / 64;
    const int E = in_sizes[1] / 2;
    const int* rows = idx;
    const int* cols = idx + E;

    static int nsm = 0;
    if (nsm == 0) {
        cudaDeviceGetAttribute(&nsm, cudaDevAttrMultiProcessorCount, 0);
        if (nsm <= 0 || nsm > 1024) nsm = 148;
        cudaFuncSetAttribute(edge_kernel,
                             cudaFuncAttributeMaxDynamicSharedMemorySize,
                             SMEM_FLOATS * (int)sizeof(float));
    }

    node_u_kernel<<<(N + 63) / 64, 256>>>(feats, W1, N);

    const int EB = (E + 127) / 128;
    edge_kernel<<<nsm, 256, SMEM_FLOATS * sizeof(float)>>>(
        rows, cols, feats, W1, b1, W2, b2, W3, b3, E, EB);

    reduce_partials_kernel<<<1, 256>>>(nsm);

    finalize_kernel<<<(N + 15) / 16, 256>>>(out, N);
}

// round 12
// speedup vs baseline: 1.1091x; 1.0107x over previous
#include <cuda_runtime.h>
#include <math.h>

#define SPH 132            // Fcs/H1s row stride (floats)
#define H2P 130            // H2s row stride (floats)

// dynamic smem layout (floats) — padded for unconditional prefetch
#define OFF_W1B 0          // [128 m][64 k] + 16 pad          8208
#define OFF_W2  8208       // [128 m][128 k] + 16 pad        16400
#define OFF_FCS 24608      // [65 k][SPH] (row 64 = pad)      8580
#define OFF_H1  33188      // [129 m][SPH] (row 128 = pad)   17028
#define OFF_US  50216      // [8 row][128 m]                  1024
#define SMEM_FLOATS 51240  // 204960 bytes

// ---------------- device scratch -------------------------------------------
__device__ float  g_U[(size_t)50000 * 128];  // exact 64-term prefix chains
__device__ float  g_z[800000];               // fp32 z (bitwise target)
__device__ double g_part[1024];              // per-CTA sum of z^2 (fp64)
__device__ int    g_arrive;                  // grid barrier (self-cleaning)
__device__ int    g_depart;

// ---------------- f32x2 helpers (two independent fp32 FMAs, bitwise = fmaf) -
static __device__ __forceinline__ unsigned long long ffma2(
    unsigned long long a, unsigned long long b, unsigned long long c) {
    unsigned long long d;
    asm("fma.rn.f32x2 %0, %1, %2, %3;" : "=l"(d) : "l"(a), "l"(b), "l"(c));
    return d;
}
static __device__ __forceinline__ unsigned long long dup2(float a) {
    unsigned long long d; unsigned int ai = __float_as_uint(a);
    asm("mov.b64 %0, {%1, %1};" : "=l"(d) : "r"(ai));
    return d;
}
static __device__ __forceinline__ void unpack2(unsigned long long v, float& lo, float& hi) {
    unsigned int l, h;
    asm("mov.b64 {%0, %1}, %2;" : "=r"(l), "=r"(h) : "l"(v));
    lo = __uint_as_float(l); hi = __uint_as_float(h);
}

// ---------------- stage 1: U[n][m] = serial FMA chain over k=0..63 ----------
__global__ __launch_bounds__(256)
void node_u_kernel(const float* __restrict__ feats,
                   const float* __restrict__ W1, int N)
{
    __shared__ float fs[64 * 64];
    const int tid = threadIdx.x;
    const int h = tid & 127;
    const int half = tid >> 7;
    const int n0 = blockIdx.x * 64;
    int cnt = N - n0; if (cnt > 64) cnt = 64;
    if (cnt <= 0) return;

    float w[64];
    const float4* wp = (const float4*)(W1 + h * 128);
#pragma unroll
    for (int i = 0; i < 16; i++) {
        float4 q = __ldg(wp + i);
        w[4*i] = q.x; w[4*i+1] = q.y; w[4*i+2] = q.z; w[4*i+3] = q.w;
    }
    const float4* fsrc = (const float4*)(feats + (size_t)n0 * 64);
    for (int i = tid; i < cnt * 16; i += 256)
        ((float4*)fs)[i] = __ldg(fsrc + i);
    __syncthreads();

    const int nb = half * 32;
    const int ne = (cnt < nb + 32) ? cnt : (nb + 32);
    for (int nn = nb; nn < ne; nn++) {
        const float* fp = fs + nn * 64;
        float acc = 0.f;
#pragma unroll
        for (int k = 0; k < 64; k++) acc = fmaf(w[k], fp[k], acc);  // serial ascending
        g_U[(size_t)(n0 + nn) * 128 + h] = acc;
    }
}

// ---------------- gather helper (strided over `nt` threads) -----------------
static __device__ __forceinline__ void gather_tile(
    float* Fcs, float* Us, const int* rows, const int* cols,
    const float* feats, int e0, int E, int t, int nt)
{
    for (int idx = t; idx < 2048; idx += nt) {
        int e = idx >> 4, kq = idx & 15;
        int g = e0 + e;
        float4 q = make_float4(0.f, 0.f, 0.f, 0.f);
        if (g < E) {
            int c = __ldg(cols + g);
            q = __ldg((const float4*)(feats + (size_t)c * 64) + kq);
        }
        Fcs[(kq*4+0)*SPH + e] = q.x;
        Fcs[(kq*4+1)*SPH + e] = q.y;
        Fcs[(kq*4+2)*SPH + e] = q.z;
        Fcs[(kq*4+3)*SPH + e] = q.w;
    }
    for (int i = t; i < 1024; i += nt) {
        int r = i >> 7, m = i & 127;
        int ge = e0 + r * 16;
        int grow = (ge < E) ? __ldg(rows + ge) : 0;
        Us[i] = g_U[(size_t)grow * 128 + m];
    }
}

// ---------------- stage 2: persistent fused kernel (layers 1-3 + mask) ------
// 256 threads: tx = tid&15 (8 edges: tx*4.. and 64+tx*4..), ty = tid>>4 (8 m)
__global__ __launch_bounds__(256, 1)
void edge_kernel(const int* __restrict__ rows, const int* __restrict__ cols,
                 const float* __restrict__ feats,
                 const float* __restrict__ W1g, const float* __restrict__ b1g,
                 const float* __restrict__ W2g, const float* __restrict__ b2g,
                 const float* __restrict__ W3g, const float* __restrict__ b3g,
                 float* __restrict__ out, int E, int EB, int Nn)
{
    extern __shared__ float smem[];
    float* W1bs = smem + OFF_W1B;
    float* W2s  = smem + OFF_W2;
    float* Fcs  = smem + OFF_FCS;
    float* H1s  = smem + OFF_H1;
    float* H2s  = H1s;                  // phase C alias: [128 e][H2P]
    float* Us   = smem + OFF_US;

    __shared__ float  W3s[128];
    __shared__ double dred[4];
    __shared__ float  snorm;

    const int tid = threadIdx.x;

    // ---- resident weights (loaded once) ----
    {
        const float4* w1v = (const float4*)W1g;
#pragma unroll
        for (int it = 0; it < 8; it++) {
            int idx = tid + it * 256;
            int m = idx >> 4, kq = idx & 15;
            *((float4*)(W1bs + m * 64 + kq * 4)) = __ldg(w1v + m * 32 + 16 + kq);
        }
        const float4* src = (const float4*)W2g;
#pragma unroll 4
        for (int it = 0; it < 16; it++) {
            int idx = tid + it * 256;
            *((float4*)(W2s + idx * 4)) = __ldg(src + idx);
        }
        if (tid < 128) W3s[tid] = __ldg(W3g + tid);
    }

    const int tx = tid & 15, ty = tid >> 4;
    const float b3v = __ldg(b3g);
    float bb1[8], bb2[8];
#pragma unroll
    for (int i = 0; i < 8; i++) {
        int m = (i < 4) ? (ty*4 + i) : (64 + ty*4 + (i-4));
        bb1[i] = __ldg(b1g + m);
        bb2[i] = __ldg(b2g + m);
    }
    double sq_acc = 0.0;

    int tile = blockIdx.x;
    if (tile < EB)
        gather_tile(Fcs, Us, rows, cols, feats, tile * 128, E, tid, 256);
    __syncthreads();

    for (; tile < EB; tile += gridDim.x) {
        const int e0 = tile * 128;
        unsigned long long acc[8][4];

        // ================= phase A: layer-1 chain over k=64..127 ===========
        {
            const int rA = tx >> 2, rB = 4 + (tx >> 2);
#pragma unroll
            for (int i = 0; i < 8; i++) {
                int m = (i < 4) ? (ty*4 + i) : (64 + ty*4 + (i-4));
                unsigned long long uA = dup2(Us[rA*128 + m]);
                unsigned long long uB = dup2(Us[rB*128 + m]);
                acc[i][0] = uA; acc[i][1] = uA;
                acc[i][2] = uB; acc[i][3] = uB;
            }
            const float* a0p = W1bs + (ty*4) * 64;
            const float* a1p = W1bs + (64 + ty*4) * 64;

            ulonglong2 q0 = *(const ulonglong2*)(Fcs + tx*4);
            ulonglong2 q1 = *(const ulonglong2*)(Fcs + 64 + tx*4);

#pragma unroll 2
            for (int k4 = 0; k4 < 16; k4++) {
                float a[8][4];
#pragma unroll
                for (int i = 0; i < 4; i++) {
                    float4 q  = *(const float4*)(a0p + i*64 + k4*4);
                    a[i][0]=q.x; a[i][1]=q.y; a[i][2]=q.z; a[i][3]=q.w;
                    float4 q2 = *(const float4*)(a1p + i*64 + k4*4);
                    a[4+i][0]=q2.x; a[4+i][1]=q2.y; a[4+i][2]=q2.z; a[4+i][3]=q2.w;
                }
#pragma unroll
                for (int kk = 0; kk < 4; kk++) {
                    const float* bn = Fcs + (k4*4 + kk + 1) * SPH;   // padded prefetch
                    ulonglong2 n0 = *(const ulonglong2*)(bn + tx*4);
                    ulonglong2 n1 = *(const ulonglong2*)(bn + 64 + tx*4);
                    unsigned long long ad[8];
#pragma unroll
                    for (int i = 0; i < 8; i++) ad[i] = dup2(a[i][kk]);
                    // group by shared b-operand: 8 consecutive FFMA2 share q0.x etc.
#pragma unroll
                    for (int i = 0; i < 8; i++) acc[i][0] = ffma2(ad[i], q0.x, acc[i][0]);
#pragma unroll
                    for (int i = 0; i < 8; i++) acc[i][1] = ffma2(ad[i], q0.y, acc[i][1]);
#pragma unroll
                    for (int i = 0; i < 8; i++) acc[i][2] = ffma2(ad[i], q1.x, acc[i][2]);
#pragma unroll
                    for (int i = 0; i < 8; i++) acc[i][3] = ffma2(ad[i], q1.y, acc[i][3]);
                    q0 = n0; q1 = n1;
                }
            }
#pragma unroll
            for (int i = 0; i < 8; i++) {
                int m = (i < 4) ? (ty*4 + i) : (64 + ty*4 + (i-4));
                float bb = bb1[i];
#pragma unroll
                for (int p = 0; p < 4; p++) {
                    float lo, hi; unpack2(acc[i][p], lo, hi);
                    int e = (p < 2) ? (tx*4 + p*2) : (64 + tx*4 + (p-2)*2);
                    H1s[m*SPH + e]     = fmaxf(lo + bb, 0.f);
                    H1s[m*SPH + e + 1] = fmaxf(hi + bb, 0.f);
                }
            }
        }
        __syncthreads();

        // ================= phase B: layer-2 serial ascending-k chain ========
#pragma unroll
        for (int i = 0; i < 8; i++)
#pragma unroll
            for (int p = 0; p < 4; p++) acc[i][p] = 0ULL;
        {
            const float* a0p = W2s + (ty*4) * 128;
            const float* a1p = W2s + (64 + ty*4) * 128;

            ulonglong2 q0 = *(const ulonglong2*)(H1s + tx*4);
            ulonglong2 q1 = *(const ulonglong2*)(H1s + 64 + tx*4);

#pragma unroll 2
            for (int k4 = 0; k4 < 32; k4++) {
                float a[8][4];
#pragma unroll
                for (int i = 0; i < 4; i++) {
                    float4 q  = *(const float4*)(a0p + i*128 + k4*4);
                    a[i][0]=q.x; a[i][1]=q.y; a[i][2]=q.z; a[i][3]=q.w;
                    float4 q2 = *(const float4*)(a1p + i*128 + k4*4);
                    a[4+i][0]=q2.x; a[4+i][1]=q2.y; a[4+i][2]=q2.z; a[4+i][3]=q2.w;
                }
#pragma unroll
                for (int kk = 0; kk < 4; kk++) {
                    const float* bn = H1s + (k4*4 + kk + 1) * SPH;   // padded prefetch
                    ulonglong2 n0 = *(const ulonglong2*)(bn + tx*4);
                    ulonglong2 n1 = *(const ulonglong2*)(bn + 64 + tx*4);
                    unsigned long long ad[8];
#pragma unroll
                    for (int i = 0; i < 8; i++) ad[i] = dup2(a[i][kk]);
#pragma unroll
                    for (int i = 0; i < 8; i++) acc[i][0] = ffma2(ad[i], q0.x, acc[i][0]);
#pragma unroll
                    for (int i = 0; i < 8; i++) acc[i][1] = ffma2(ad[i], q0.y, acc[i][1]);
#pragma unroll
                    for (int i = 0; i < 8; i++) acc[i][2] = ffma2(ad[i], q1.x, acc[i][2]);
#pragma unroll
                    for (int i = 0; i < 8; i++) acc[i][3] = ffma2(ad[i], q1.y, acc[i][3]);
                    q0 = n0; q1 = n1;
                }
            }
        }
        __syncthreads();   // all H1s reads done before aliasing it as H2s
#pragma unroll
        for (int i = 0; i < 8; i++) {
            int m = (i < 4) ? (ty*4 + i) : (64 + ty*4 + (i-4));
            float bb = bb2[i];
#pragma unroll
            for (int p = 0; p < 4; p++) {
                float lo, hi; unpack2(acc[i][p], lo, hi);
                int e = (p < 2) ? (tx*4 + p*2) : (64 + tx*4 + (p-2)*2);
                H2s[e*H2P + m]     = fmaxf(lo + bb, 0.f);
                H2s[(e+1)*H2P + m] = fmaxf(hi + bb, 0.f);
            }
        }
        __syncthreads();

        // ---- phase C (tid<128): z chain; tid>=128: prefetch next tile ----
        if (tid < 128) {
            const float* hrow = H2s + tid * H2P;
            float z = 0.f;
#pragma unroll
            for (int m = 0; m < 128; m++)
                z = fmaf(W3s[m], hrow[m], z);      // serial, ascending (GEMM order)
            z = z + b3v;                           // b3 = 0: exact

            int g = e0 + tid;
            if (g < E) {
                g_z[g] = z;
                sq_acc += (double)z * (double)z;
            }
        } else {
            int nt = tile + gridDim.x;
            if (nt < EB)
                gather_tile(Fcs, Us, rows, cols, feats, nt * 128, E, tid - 128, 128);
        }
        __syncthreads();
    }

    // ---- per-CTA deterministic sum of z^2 ----
    if (tid < 128) {
        double s = sq_acc;
#pragma unroll
        for (int m2 = 16; m2; m2 >>= 1)
            s += __shfl_xor_sync(0xffffffffu, s, m2);
        if ((tid & 31) == 0) dred[tid >> 5] = s;
    }
    __syncthreads();
    if (tid == 0)
        g_part[blockIdx.x] = (dred[0] + dred[1]) + (dred[2] + dred[3]);

    // ================= grid barrier (self-cleaning across graph replays) ====
    __threadfence();
    __syncthreads();
    if (tid == 0) {
        atomicAdd(&g_arrive, 1);
        while (((volatile int*)&g_arrive)[0] < (int)gridDim.x) { }
    }
    __syncthreads();
    __threadfence();

    // ---- norm: exact fp64 sum of per-CTA partials (same order every CTA) ---
    if (tid == 0) {
        double s = 0.0;
        for (int i = 0; i < (int)gridDim.x; i++) s += __ldcg(g_part + i);
        snorm = (float)fmax(sqrt(s), 1e-12);
    }
    __syncthreads();
    const float nrm = snorm;

    // ================= finalize: fp32-faithful softmax + top-8 mask ==========
    {
        const int lane = tid & 31;
        const int gw = blockIdx.x * 8 + (tid >> 5);
        const int j = lane & 15;
        for (int rp = gw; rp * 2 < Nn; rp += gridDim.x * 8) {
            const int row = rp * 2 + (lane >> 4);
            const bool valid = row < Nn;
            const int e = row * 16 + j;

            float zn = valid ? __fdiv_rn(__ldcg(g_z + e), nrm) : -1e30f;

            float mx = zn;
#pragma unroll
            for (int m = 8; m; m >>= 1)
                mx = fmaxf(mx, __shfl_xor_sync(0xffffffffu, mx, m, 16));

            const float a = zn - mx;                       // fp32 subtract, as ref
            float ez = (float)exp((double)a);              // ~correctly-rounded expf
            if (!valid) ez = 0.f;

            float s = 0.f;                                 // ascending index order
#pragma unroll
            for (int i = 0; i < 16; i++)
                s += __shfl_sync(0xffffffffu, ez, i, 16);

            const float pi = __fdiv_rn(ez, s);

            int r = 0;
#pragma unroll
            for (int i = 0; i < 16; i++) {
                float v = __shfl_sync(0xffffffffu, pi, i, 16);
                r += (v > pi) ? 1 : 0;
            }
            if (valid) out[e] = (r <= 7) ? pi : 0.f;       // top-8, ties kept
        }
    }

    // ---- barrier state reset (last departer) ----
    __syncthreads();
    if (tid == 0) {
        int old = atomicAdd(&g_depart, 1);
        if (old == (int)gridDim.x - 1) { g_arrive = 0; g_depart = 0; }
    }
}

// ---------------- launch ----------------------------------------------------
extern "C" void kernel_launch(void* const* d_in, const int* in_sizes, int n_in,
                              void* d_out, int out_size)
{
    const float* feats = (const float*)d_in[0];
    const int*   idx   = (const int*)  d_in[1];
    const float* W1    = (const float*)d_in[2];
    const float* b1    = (const float*)d_in[3];
    const float* W2    = (const float*)d_in[4];
    const float* b2    = (const float*)d_in[5];
    const float* W3    = (const float*)d_in[6];
    const float* b3    = (const float*)d_in[7];
    float* out = (float*)d_out;

    const int N = in_sizes[0] / 64;
    const int E = in_sizes[1] / 2;
    const int* rows = idx;
    const int* cols = idx + E;

    static int nsm = 0;
    if (nsm == 0) {
        cudaDeviceGetAttribute(&nsm, cudaDevAttrMultiProcessorCount, 0);
        if (nsm <= 0 || nsm > 1024) nsm = 148;
        cudaFuncSetAttribute(edge_kernel,
                             cudaFuncAttributeMaxDynamicSharedMemorySize,
                             SMEM_FLOATS * (int)sizeof(float));
    }

    node_u_kernel<<<(N + 63) / 64, 256>>>(feats, W1, N);

    const int EB = (E + 127) / 128;
    edge_kernel<<<nsm, 256, SMEM_FLOATS * sizeof(float)>>>(
        rows, cols, feats, W1, b1, W2, b2, W3, b3, out, E, EB, N);
}

// round 13
// speedup vs baseline: 1.1182x; 1.0082x over previous
#include <cuda_runtime.h>
#include <math.h>

#define SPH 132            // Fcs/H1s row stride (floats)
#define H2P 130            // H2s row stride (floats)

// dynamic smem layout (floats) — padded for unconditional prefetch
#define OFF_W1B 0          // [128 m][64 k] + 16 pad          8208
#define OFF_W2  8208       // [128 m][128 k] + 16 pad        16400
#define OFF_FCS 24608      // [65 k][SPH] (row 64 = pad)      8580
#define OFF_H1  33188      // [129 m][SPH] (row 128 = pad)   17028
#define OFF_US  50216      // [8 row][128 m]                  1024
#define SMEM_FLOATS 51240  // 204960 bytes

// ---------------- device scratch -------------------------------------------
__device__ float  g_U[(size_t)50000 * 128];  // exact 64-term prefix chains
__device__ float  g_z[800000];               // fp32 z (bitwise target)
__device__ double g_part[1024];              // per-CTA sum of z^2 (fp64)
__device__ int    g_arrive;                  // grid barrier (self-cleaning)
__device__ int    g_depart;

// ---------------- f32x2 helpers (two independent fp32 FMAs, bitwise = fmaf) -
static __device__ __forceinline__ unsigned long long ffma2(
    unsigned long long a, unsigned long long b, unsigned long long c) {
    unsigned long long d;
    asm("fma.rn.f32x2 %0, %1, %2, %3;" : "=l"(d) : "l"(a), "l"(b), "l"(c));
    return d;
}
static __device__ __forceinline__ unsigned long long dup2(float a) {
    unsigned long long d; unsigned int ai = __float_as_uint(a);
    asm("mov.b64 %0, {%1, %1};" : "=l"(d) : "r"(ai));
    return d;
}
static __device__ __forceinline__ void unpack2(unsigned long long v, float& lo, float& hi) {
    unsigned int l, h;
    asm("mov.b64 {%0, %1}, %2;" : "=r"(l), "=r"(h) : "l"(v));
    lo = __uint_as_float(l); hi = __uint_as_float(h);
}

// ---------------- gather helper (strided over `nt` threads) -----------------
static __device__ __forceinline__ void gather_tile(
    float* Fcs, float* Us, const int* rows, const int* cols,
    const float* feats, int e0, int E, int t, int nt)
{
    for (int idx = t; idx < 2048; idx += nt) {
        int e = idx >> 4, kq = idx & 15;
        int g = e0 + e;
        float4 q = make_float4(0.f, 0.f, 0.f, 0.f);
        if (g < E) {
            int c = __ldg(cols + g);
            q = __ldg((const float4*)(feats + (size_t)c * 64) + kq);
        }
        Fcs[(kq*4+0)*SPH + e] = q.x;
        Fcs[(kq*4+1)*SPH + e] = q.y;
        Fcs[(kq*4+2)*SPH + e] = q.z;
        Fcs[(kq*4+3)*SPH + e] = q.w;
    }
    for (int i = t; i < 1024; i += nt) {
        int r = i >> 7, m = i & 127;
        int ge = e0 + r * 16;
        int grow = (ge < E) ? __ldg(rows + ge) : 0;
        Us[i] = g_U[(size_t)grow * 128 + m];
    }
}

// ---------------- persistent fused kernel: U prologue + layers 1-3 + mask ---
// 256 threads: tx = tid&15 (8 edges: tx*4.. and 64+tx*4..), ty = tid>>4 (8 m)
__global__ __launch_bounds__(256, 1)
void edge_kernel(const int* __restrict__ rows, const int* __restrict__ cols,
                 const float* __restrict__ feats,
                 const float* __restrict__ W1g, const float* __restrict__ b1g,
                 const float* __restrict__ W2g, const float* __restrict__ b2g,
                 const float* __restrict__ W3g, const float* __restrict__ b3g,
                 float* __restrict__ out, int E, int EB, int Nn)
{
    extern __shared__ float smem[];
    float* W1bs = smem + OFF_W1B;
    float* W2s  = smem + OFF_W2;
    float* Fcs  = smem + OFF_FCS;
    float* H1s  = smem + OFF_H1;
    float* H2s  = H1s;                  // phase C alias: [128 e][H2P]
    float* Us   = smem + OFF_US;

    __shared__ float  W3s[128];
    __shared__ double dred[4];
    __shared__ float  snorm;

    const int tid = threadIdx.x;

    // ---- resident weights (loaded once) ----
    {
        const float4* w1v = (const float4*)W1g;
#pragma unroll
        for (int it = 0; it < 8; it++) {
            int idx = tid + it * 256;
            int m = idx >> 4, kq = idx & 15;
            *((float4*)(W1bs + m * 64 + kq * 4)) = __ldg(w1v + m * 32 + 16 + kq);
        }
        const float4* src = (const float4*)W2g;
#pragma unroll 4
        for (int it = 0; it < 16; it++) {
            int idx = tid + it * 256;
            *((float4*)(W2s + idx * 4)) = __ldg(src + idx);
        }
        if (tid < 128) W3s[tid] = __ldg(W3g + tid);
    }

    // ================= per-CTA U prologue (replaces node_u kernel) ==========
    // Tile t covers rows 8t..8t+7; tiles partition across CTAs, so each CTA
    // computes exactly the U rows its own tiles consume. Same serial
    // ascending-k fmaf chain as before -> bitwise identical U values.
    {
        const int m = tid & 127;
        const int half = tid >> 7;
        float w[64];
        const float4* wp = (const float4*)(W1g + m * 128);
#pragma unroll
        for (int i = 0; i < 16; i++) {
            float4 q = __ldg(wp + i);
            w[4*i] = q.x; w[4*i+1] = q.y; w[4*i+2] = q.z; w[4*i+3] = q.w;
        }
        const int NR = (E + 15) / 16;   // number of rows
        for (int t = blockIdx.x; t < EB; t += gridDim.x) {
            const int r0 = t * 8;
            if (tid < 128) {            // stage 8 rows of feats into Fcs (2KB)
                int rr = tid >> 4, kq = tid & 15;
                float4 q = make_float4(0.f, 0.f, 0.f, 0.f);
                if (r0 + rr < NR)
                    q = __ldg((const float4*)(feats + (size_t)(r0 + rr) * 64) + kq);
                ((float4*)Fcs)[tid] = q;
            }
            __syncthreads();
#pragma unroll
            for (int rr = 0; rr < 4; rr++) {
                const int row = r0 + half * 4 + rr;
                const float4* fp4 = (const float4*)(Fcs + (half * 4 + rr) * 64);
                float acc = 0.f;
#pragma unroll
                for (int i = 0; i < 16; i++) {
                    float4 q = fp4[i];
                    acc = fmaf(w[4*i],   q.x, acc);
                    acc = fmaf(w[4*i+1], q.y, acc);
                    acc = fmaf(w[4*i+2], q.z, acc);
                    acc = fmaf(w[4*i+3], q.w, acc);
                }
                if (row < NR) g_U[(size_t)row * 128 + m] = acc;
            }
            __syncthreads();
        }
    }

    const int tx = tid & 15, ty = tid >> 4;
    const float b3v = __ldg(b3g);
    float bb1[8], bb2[8];
#pragma unroll
    for (int i = 0; i < 8; i++) {
        int m = (i < 4) ? (ty*4 + i) : (64 + ty*4 + (i-4));
        bb1[i] = __ldg(b1g + m);
        bb2[i] = __ldg(b2g + m);
    }
    double sq_acc = 0.0;

    int tile = blockIdx.x;
    if (tile < EB)
        gather_tile(Fcs, Us, rows, cols, feats, tile * 128, E, tid, 256);
    __syncthreads();

    for (; tile < EB; tile += gridDim.x) {
        const int e0 = tile * 128;
        unsigned long long acc[8][4];

        // ================= phase A: layer-1 chain over k=64..127 ===========
        {
            const int rA = tx >> 2, rB = 4 + (tx >> 2);
#pragma unroll
            for (int i = 0; i < 8; i++) {
                int m = (i < 4) ? (ty*4 + i) : (64 + ty*4 + (i-4));
                unsigned long long uA = dup2(Us[rA*128 + m]);
                unsigned long long uB = dup2(Us[rB*128 + m]);
                acc[i][0] = uA; acc[i][1] = uA;
                acc[i][2] = uB; acc[i][3] = uB;
            }
            const float* a0p = W1bs + (ty*4) * 64;
            const float* a1p = W1bs + (64 + ty*4) * 64;

            ulonglong2 q0 = *(const ulonglong2*)(Fcs + tx*4);
            ulonglong2 q1 = *(const ulonglong2*)(Fcs + 64 + tx*4);

#pragma unroll 2
            for (int k4 = 0; k4 < 16; k4++) {
                float a[8][4];
#pragma unroll
                for (int i = 0; i < 4; i++) {
                    float4 q  = *(const float4*)(a0p + i*64 + k4*4);
                    a[i][0]=q.x; a[i][1]=q.y; a[i][2]=q.z; a[i][3]=q.w;
                    float4 q2 = *(const float4*)(a1p + i*64 + k4*4);
                    a[4+i][0]=q2.x; a[4+i][1]=q2.y; a[4+i][2]=q2.z; a[4+i][3]=q2.w;
                }
#pragma unroll
                for (int kk = 0; kk < 4; kk++) {
                    const float* bn = Fcs + (k4*4 + kk + 1) * SPH;   // padded prefetch
                    ulonglong2 n0 = *(const ulonglong2*)(bn + tx*4);
                    ulonglong2 n1 = *(const ulonglong2*)(bn + 64 + tx*4);
                    unsigned long long ad[8];
#pragma unroll
                    for (int i = 0; i < 8; i++) ad[i] = dup2(a[i][kk]);
#pragma unroll
                    for (int i = 0; i < 8; i++) acc[i][0] = ffma2(ad[i], q0.x, acc[i][0]);
#pragma unroll
                    for (int i = 0; i < 8; i++) acc[i][1] = ffma2(ad[i], q0.y, acc[i][1]);
#pragma unroll
                    for (int i = 0; i < 8; i++) acc[i][2] = ffma2(ad[i], q1.x, acc[i][2]);
#pragma unroll
                    for (int i = 0; i < 8; i++) acc[i][3] = ffma2(ad[i], q1.y, acc[i][3]);
                    q0 = n0; q1 = n1;
                }
            }
#pragma unroll
            for (int i = 0; i < 8; i++) {
                int m = (i < 4) ? (ty*4 + i) : (64 + ty*4 + (i-4));
                float bb = bb1[i];
#pragma unroll
                for (int p = 0; p < 4; p++) {
                    float lo, hi; unpack2(acc[i][p], lo, hi);
                    int e = (p < 2) ? (tx*4 + p*2) : (64 + tx*4 + (p-2)*2);
                    H1s[m*SPH + e]     = fmaxf(lo + bb, 0.f);
                    H1s[m*SPH + e + 1] = fmaxf(hi + bb, 0.f);
                }
            }
        }
        __syncthreads();

        // ================= phase B: layer-2 serial ascending-k chain ========
#pragma unroll
        for (int i = 0; i < 8; i++)
#pragma unroll
            for (int p = 0; p < 4; p++) acc[i][p] = 0ULL;
        {
            const float* a0p = W2s + (ty*4) * 128;
            const float* a1p = W2s + (64 + ty*4) * 128;

            ulonglong2 q0 = *(const ulonglong2*)(H1s + tx*4);
            ulonglong2 q1 = *(const ulonglong2*)(H1s + 64 + tx*4);

#pragma unroll 2
            for (int k4 = 0; k4 < 32; k4++) {
                float a[8][4];
#pragma unroll
                for (int i = 0; i < 4; i++) {
                    float4 q  = *(const float4*)(a0p + i*128 + k4*4);
                    a[i][0]=q.x; a[i][1]=q.y; a[i][2]=q.z; a[i][3]=q.w;
                    float4 q2 = *(const float4*)(a1p + i*128 + k4*4);
                    a[4+i][0]=q2.x; a[4+i][1]=q2.y; a[4+i][2]=q2.z; a[4+i][3]=q2.w;
                }
#pragma unroll
                for (int kk = 0; kk < 4; kk++) {
                    const float* bn = H1s + (k4*4 + kk + 1) * SPH;   // padded prefetch
                    ulonglong2 n0 = *(const ulonglong2*)(bn + tx*4);
                    ulonglong2 n1 = *(const ulonglong2*)(bn + 64 + tx*4);
                    unsigned long long ad[8];
#pragma unroll
                    for (int i = 0; i < 8; i++) ad[i] = dup2(a[i][kk]);
#pragma unroll
                    for (int i = 0; i < 8; i++) acc[i][0] = ffma2(ad[i], q0.x, acc[i][0]);
#pragma unroll
                    for (int i = 0; i < 8; i++) acc[i][1] = ffma2(ad[i], q0.y, acc[i][1]);
#pragma unroll
                    for (int i = 0; i < 8; i++) acc[i][2] = ffma2(ad[i], q1.x, acc[i][2]);
#pragma unroll
                    for (int i = 0; i < 8; i++) acc[i][3] = ffma2(ad[i], q1.y, acc[i][3]);
                    q0 = n0; q1 = n1;
                }
            }
        }
        __syncthreads();   // all H1s reads done before aliasing it as H2s
#pragma unroll
        for (int i = 0; i < 8; i++) {
            int m = (i < 4) ? (ty*4 + i) : (64 + ty*4 + (i-4));
            float bb = bb2[i];
#pragma unroll
            for (int p = 0; p < 4; p++) {
                float lo, hi; unpack2(acc[i][p], lo, hi);
                int e = (p < 2) ? (tx*4 + p*2) : (64 + tx*4 + (p-2)*2);
                H2s[e*H2P + m]     = fmaxf(lo + bb, 0.f);
                H2s[(e+1)*H2P + m] = fmaxf(hi + bb, 0.f);
            }
        }
        __syncthreads();

        // ---- phase C (tid<128): z chain; tid>=128: prefetch next tile ----
        if (tid < 128) {
            const float* hrow = H2s + tid * H2P;
            float z = 0.f;
#pragma unroll
            for (int m = 0; m < 128; m++)
                z = fmaf(W3s[m], hrow[m], z);      // serial, ascending (GEMM order)
            z = z + b3v;                           // b3 = 0: exact

            int g = e0 + tid;
            if (g < E) {
                g_z[g] = z;
                sq_acc += (double)z * (double)z;
            }
        } else {
            int nt = tile + gridDim.x;
            if (nt < EB)
                gather_tile(Fcs, Us, rows, cols, feats, nt * 128, E, tid - 128, 128);
        }
        __syncthreads();
    }

    // ---- per-CTA deterministic sum of z^2 ----
    if (tid < 128) {
        double s = sq_acc;
#pragma unroll
        for (int m2 = 16; m2; m2 >>= 1)
            s += __shfl_xor_sync(0xffffffffu, s, m2);
        if ((tid & 31) == 0) dred[tid >> 5] = s;
    }
    __syncthreads();
    if (tid == 0)
        g_part[blockIdx.x] = (dred[0] + dred[1]) + (dred[2] + dred[3]);

    // ================= grid barrier (self-cleaning across graph replays) ====
    __threadfence();
    __syncthreads();
    if (tid == 0) {
        atomicAdd(&g_arrive, 1);
        while (((volatile int*)&g_arrive)[0] < (int)gridDim.x) { }
    }
    __syncthreads();
    __threadfence();

    // ---- norm: exact fp64 sum of per-CTA partials (same order every CTA) ---
    if (tid == 0) {
        double s = 0.0;
        for (int i = 0; i < (int)gridDim.x; i++) s += __ldcg(g_part + i);
        snorm = (float)fmax(sqrt(s), 1e-12);
    }
    __syncthreads();
    const float nrm = snorm;

    // ================= finalize: fp32-faithful softmax + top-8 mask ==========
    {
        const int lane = tid & 31;
        const int gw = blockIdx.x * 8 + (tid >> 5);
        const int j = lane & 15;
        for (int rp = gw; rp * 2 < Nn; rp += gridDim.x * 8) {
            const int row = rp * 2 + (lane >> 4);
            const bool valid = row < Nn;
            const int e = row * 16 + j;

            float zn = valid ? __fdiv_rn(__ldcg(g_z + e), nrm) : -1e30f;

            float mx = zn;
#pragma unroll
            for (int m = 8; m; m >>= 1)
                mx = fmaxf(mx, __shfl_xor_sync(0xffffffffu, mx, m, 16));

            const float a = zn - mx;                       // fp32 subtract, as ref
            float ez = (float)exp((double)a);              // ~correctly-rounded expf
            if (!valid) ez = 0.f;

            float s = 0.f;                                 // ascending index order
#pragma unroll
            for (int i = 0; i < 16; i++)
                s += __shfl_sync(0xffffffffu, ez, i, 16);

            const float pi = __fdiv_rn(ez, s);

            int r = 0;
#pragma unroll
            for (int i = 0; i < 16; i++) {
                float v = __shfl_sync(0xffffffffu, pi, i, 16);
                r += (v > pi) ? 1 : 0;
            }
            if (valid) out[e] = (r <= 7) ? pi : 0.f;       // top-8, ties kept
        }
    }

    // ---- barrier state reset (last departer) ----
    __syncthreads();
    if (tid == 0) {
        int old = atomicAdd(&g_depart, 1);
        if (old == (int)gridDim.x - 1) { g_arrive = 0; g_depart = 0; }
    }
}

// ---------------- launch ----------------------------------------------------
extern "C" void kernel_launch(void* const* d_in, const int* in_sizes, int n_in,
                              void* d_out, int out_size)
{
    const float* feats = (const float*)d_in[0];
    const int*   idx   = (const int*)  d_in[1];
    const float* W1    = (const float*)d_in[2];
    const float* b1    = (const float*)d_in[3];
    const float* W2    = (const float*)d_in[4];
    const float* b2    = (const float*)d_in[5];
    const float* W3    = (const float*)d_in[6];
    const float* b3    = (const float*)d_in[7];
    float* out = (float*)d_out;

    const int N = in_sizes[0] / 64;
    const int E = in_sizes[1] / 2;
    const int* rows = idx;
    const int* cols = idx + E;

    static int nsm = 0;
    if (nsm == 0) {
        cudaDeviceGetAttribute(&nsm, cudaDevAttrMultiProcessorCount, 0);
        if (nsm <= 0 || nsm > 1024) nsm = 148;
        cudaFuncSetAttribute(edge_kernel,
                             cudaFuncAttributeMaxDynamicSharedMemorySize,
                             SMEM_FLOATS * (int)sizeof(float));
    }

    const int EB = (E + 127) / 128;
    edge_kernel<<<nsm, 256, SMEM_FLOATS * sizeof(float)>>>(
        rows, cols, feats, W1, b1, W2, b2, W3, b3, out, E, EB, N);
}